// round 13
// baseline (speedup 1.0000x reference)
#include <cuda_runtime.h>
#include <cstdint>
#include <cstddef>

#define HLD 132
#define ESZ (64 * HLD)  // 8448 floats
// smem floats: Wb 10240 (5 sub-slab bufs x 2048) | E 8448 | H 8448 | ws 640 | gbs 512 | zb 320
#define SMEM_FLOATS (10240 + ESZ + ESZ + 640 + 512 + 320)
#define SMEM_BYTES (SMEM_FLOATS * 4)

__device__ __align__(16) float g_W2[131072];  // [slab32][kt4][nt16][lane32][e2] tf32
__device__ float g_gb[512];
__device__ float g_ca[16384], g_cb[16384], g_cc[16384];
__device__ float g_mom[640];
__device__ float g_mu2[640], g_rs2[640];

__device__ __forceinline__ uint32_t tf32u(float f) {
  uint32_t u;
  asm("cvt.rna.tf32.f32 %0,%1;" : "=r"(u) : "f"(f));
  return u;
}
__device__ __forceinline__ float tf32f(float f) { return __uint_as_float(tf32u(f)); }
__device__ __forceinline__ float tanh_ap(float x) {
  float y;
  asm("tanh.approx.f32 %0,%1;" : "=f"(y) : "f"(x));
  return y;
}
__device__ __forceinline__ float sig_ap(float x) {
  return fmaf(tanh_ap(0.5f * x), 0.5f, 0.5f);
}
__device__ __forceinline__ void mma8(float (&d)[4], float a0, float a1, float a2,
                                     float a3, float b0, float b1) {
  asm volatile(
      "mma.sync.aligned.m16n8k8.row.col.f32.tf32.tf32.f32 "
      "{%0,%1,%2,%3},{%4,%5,%6,%7},{%8,%9},{%0,%1,%2,%3};\n"
      : "+f"(d[0]), "+f"(d[1]), "+f"(d[2]), "+f"(d[3])
      : "r"(__float_as_uint(a0)), "r"(__float_as_uint(a1)),
        "r"(__float_as_uint(a2)), "r"(__float_as_uint(a3)),
        "r"(__float_as_uint(b0)), "r"(__float_as_uint(b1)));
}
// 8KB sub-slab copy into explicit ring buffer: 128 threads x 64B.
__device__ __forceinline__ void issue_sub(float* Wb, int content, int buf, int tid) {
  uint32_t sa = (uint32_t)__cvta_generic_to_shared(Wb + buf * 2048 + tid * 16);
  const char* gp = (const char*)(g_W2 + (size_t)content * 2048 + tid * 16);
#pragma unroll
  for (int i = 0; i < 4; i++)
    asm volatile("cp.async.cg.shared.global [%0], [%1], 16;" ::"r"(sa + 16 * i),
                 "l"(gp + 16 * i));
  asm volatile("cp.async.commit_group;" ::: "memory");
}

// ---- main recurrent kernel: 512 CTAs x 128 thr (2 CTAs/SM), 64 rows/CTA ----
__global__ void __launch_bounds__(128, 2)
    k_main(const float* __restrict__ x, const float* __restrict__ wout,
           float* __restrict__ out) {
  extern __shared__ float sm[];
  float* Wb = sm;
  float* E = sm + 10240;
  float* H = E + ESZ;
  float* ws = H + ESZ;
  float* gbs = ws + 640;
  float* zb = gbs + 512;
  const int tid = threadIdx.x, lane = tid & 31, wid = tid >> 5;
  const int rg = wid >> 1, cg = wid & 1, lg = lane >> 2, q = lane & 3;
  const int bg0 = blockIdx.x << 6;
  for (int i = tid; i < 640; i += 128) ws[i] = wout[i];
  for (int i = tid; i < 512; i += 128) gbs[i] = g_gb[i];
  for (int i = tid; i < ESZ; i += 128) H[i] = 0.f;
  float c[2][8][4], acc[2][8][4], ig[2][8][4];
#pragma unroll
  for (int m = 0; m < 2; m++)
#pragma unroll
    for (int nt = 0; nt < 8; nt++)
#pragma unroll
      for (int e = 0; e < 4; e++) c[m][nt][e] = 0.f;
  __syncthreads();
  const int er = tid >> 1;
  const size_t xo = (size_t)(bg0 + er) * 256;
  const int ar = (32 * rg + lg) * HLD;
  const int bofs[4] = {0, 256, 128, 384};  // stream i,g,f,o -> pytorch offsets

  // pipeline prologue: depth-3 — sub-slabs 0,1,2 in flight in ring bufs 0,1,2
  issue_sub(Wb, 0, 0, tid);
  issue_sub(Wb, 1, 1, tid);
  issue_sub(Wb, 2, 2, tid);
  int ibuf = 3, cbuf = 0;  // ring-of-5 cursors (persist across t; 128*64 sub-slabs)

  for (int t = 0; t < 128; t++) {
    // ---- E fill: e = relu(ca*x0+cb*x1+cc), tf32-rounded (BN1 folded) ----
    {
      float2 xv = *reinterpret_cast<const float2*>(x + xo + 2 * t);
      const int jb = (tid & 1) << 4;
      const float4* A4 = reinterpret_cast<const float4*>(g_ca + t * 128) + jb;
      const float4* B4 = reinterpret_cast<const float4*>(g_cb + t * 128) + jb;
      const float4* C4 = reinterpret_cast<const float4*>(g_cc + t * 128) + jb;
      float* Er = E + er * HLD + ((tid & 1) << 6);
#pragma unroll
      for (int i = 0; i < 16; i++) {
        float4 a = A4[i], b = B4[i], cc4 = C4[i], ev;
        ev.x = tf32f(fmaxf(fmaf(a.x, xv.x, fmaf(b.x, xv.y, cc4.x)), 0.f));
        ev.y = tf32f(fmaxf(fmaf(a.y, xv.x, fmaf(b.y, xv.y, cc4.y)), 0.f));
        ev.z = tf32f(fmaxf(fmaf(a.z, xv.x, fmaf(b.z, xv.y, cc4.z)), 0.f));
        ev.w = tf32f(fmaxf(fmaf(a.w, xv.x, fmaf(b.w, xv.y, cc4.w)), 0.f));
        *reinterpret_cast<float4*>(Er + 4 * i) = ev;
      }
    }
    for (int ss = 0; ss < 64; ss++) {
      if ((ss & 15) == 0) {
#pragma unroll
        for (int m = 0; m < 2; m++)
#pragma unroll
          for (int nt = 0; nt < 8; nt++)
#pragma unroll
            for (int e = 0; e < 4; e++) acc[m][nt][e] = 0.f;
      }
      // depth-3 prefetch, ring of 5: issue ss+3 into buf (ss+3)%5, which held
      // sub-slab ss-2 — its consumers all finished before the iter ss-1 barrier
      // that every thread (being at iter ss) has passed. Two-barrier separation.
      issue_sub(Wb, (ss + 3) & 63, ibuf, tid);
      ibuf = (ibuf == 4) ? 0 : ibuf + 1;
      asm volatile("cp.async.wait_group 3;" ::: "memory");
      __syncthreads();
      // ---- consume sub-slab ss: 2 k-tiles, warp tile 32 rows x 64 cols ----
      const float* Ab = ((ss >> 3) & 1) ? H : E;
      const float* Bb = Wb + cbuf * 2048;
      cbuf = (cbuf == 4) ? 0 : cbuf + 1;
      const int kb = ((ss >> 1) & 3) * 32 + (ss & 1) * 16;
#pragma unroll
      for (int kt = 0; kt < 2; kt++) {
        const float* ap = Ab + ar + kb + kt * 8 + q;
        float a00 = ap[0], a01 = ap[8 * HLD], a02 = ap[4], a03 = ap[8 * HLD + 4];
        float a10 = ap[16 * HLD], a11 = ap[24 * HLD];
        float a12 = ap[16 * HLD + 4], a13 = ap[24 * HLD + 4];
        const float2* bp =
            reinterpret_cast<const float2*>(Bb) + (kt * 16 + cg * 8) * 32 + lane;
#pragma unroll
        for (int nt = 0; nt < 8; nt++) {
          float2 bv = bp[nt * 32];
          mma8(acc[0][nt], a00, a01, a02, a03, bv.x, bv.y);
          mma8(acc[1][nt], a10, a11, a12, a13, bv.x, bv.y);
        }
      }
      if ((ss & 15) != 15) continue;
      const int sg = ss >> 4;
      const float* gb = gbs + bofs[sg] + cg * 64 + 2 * q;
      if (sg == 0) {  // i-gate
#pragma unroll
        for (int m = 0; m < 2; m++)
#pragma unroll
          for (int nt = 0; nt < 8; nt++) {
            float2 gv = *reinterpret_cast<const float2*>(gb + 8 * nt);
            ig[m][nt][0] = sig_ap(acc[m][nt][0] + gv.x);
            ig[m][nt][1] = sig_ap(acc[m][nt][1] + gv.y);
            ig[m][nt][2] = sig_ap(acc[m][nt][2] + gv.x);
            ig[m][nt][3] = sig_ap(acc[m][nt][3] + gv.y);
          }
      } else if (sg == 1) {  // g-gate
#pragma unroll
        for (int m = 0; m < 2; m++)
#pragma unroll
          for (int nt = 0; nt < 8; nt++) {
            float2 gv = *reinterpret_cast<const float2*>(gb + 8 * nt);
            ig[m][nt][0] *= tanh_ap(acc[m][nt][0] + gv.x);
            ig[m][nt][1] *= tanh_ap(acc[m][nt][1] + gv.y);
            ig[m][nt][2] *= tanh_ap(acc[m][nt][2] + gv.x);
            ig[m][nt][3] *= tanh_ap(acc[m][nt][3] + gv.y);
          }
      } else if (sg == 2) {  // f-gate
#pragma unroll
        for (int m = 0; m < 2; m++)
#pragma unroll
          for (int nt = 0; nt < 8; nt++) {
            float2 gv = *reinterpret_cast<const float2*>(gb + 8 * nt);
            c[m][nt][0] = fmaf(sig_ap(acc[m][nt][0] + gv.x), c[m][nt][0], ig[m][nt][0]);
            c[m][nt][1] = fmaf(sig_ap(acc[m][nt][1] + gv.y), c[m][nt][1], ig[m][nt][1]);
            c[m][nt][2] = fmaf(sig_ap(acc[m][nt][2] + gv.x), c[m][nt][2], ig[m][nt][2]);
            c[m][nt][3] = fmaf(sig_ap(acc[m][nt][3] + gv.y), c[m][nt][3], ig[m][nt][3]);
          }
      } else {  // o-gate: h, H store, z2 partials
        __syncthreads();  // all H reads of this step complete before rewrite
        float zr[4][5];
#pragma unroll
        for (int sl = 0; sl < 4; sl++)
#pragma unroll
          for (int o = 0; o < 5; o++) zr[sl][o] = 0.f;
#pragma unroll
        for (int m = 0; m < 2; m++)
#pragma unroll
          for (int nt = 0; nt < 8; nt++) {
            float2 gv = *reinterpret_cast<const float2*>(gb + 8 * nt);
            float h0 = sig_ap(acc[m][nt][0] + gv.x) * tanh_ap(c[m][nt][0]);
            float h1 = sig_ap(acc[m][nt][1] + gv.y) * tanh_ap(c[m][nt][1]);
            float h2 = sig_ap(acc[m][nt][2] + gv.x) * tanh_ap(c[m][nt][2]);
            float h3 = sig_ap(acc[m][nt][3] + gv.y) * tanh_ap(c[m][nt][3]);
            const int col = cg * 64 + nt * 8 + 2 * q;
            const int ro = ar + 16 * m * HLD + col;
            *reinterpret_cast<float2*>(H + ro) = make_float2(tf32f(h0), tf32f(h1));
            *reinterpret_cast<float2*>(H + ro + 8 * HLD) =
                make_float2(tf32f(h2), tf32f(h3));
#pragma unroll
            for (int o = 0; o < 5; o++) {
              float2 wv = *reinterpret_cast<const float2*>(ws + o * 128 + col);
              zr[2 * m][o] = fmaf(h0, wv.x, fmaf(h1, wv.y, zr[2 * m][o]));
              zr[2 * m + 1][o] = fmaf(h2, wv.x, fmaf(h3, wv.y, zr[2 * m + 1][o]));
            }
          }
#pragma unroll
        for (int sl = 0; sl < 4; sl++)
#pragma unroll
          for (int o = 0; o < 5; o++) {
            zr[sl][o] += __shfl_xor_sync(0xffffffffu, zr[sl][o], 1);
            zr[sl][o] += __shfl_xor_sync(0xffffffffu, zr[sl][o], 2);
          }
        if (cg == 0 && q == 0) {
#pragma unroll
          for (int sl = 0; sl < 4; sl++)
#pragma unroll
            for (int o = 0; o < 5; o++)
              zb[(32 * rg + lg + 8 * sl) * 5 + o] = zr[sl][o];
        }
        __syncthreads();
        if (cg == 1 && q == 0) {
#pragma unroll
          for (int sl = 0; sl < 4; sl++) {
            int row = 32 * rg + lg + 8 * sl;
            size_t ob = ((size_t)(bg0 + row) * 128 + t) * 5;
#pragma unroll
            for (int o = 0; o < 5; o++) out[ob + o] = zr[sl][o] + zb[row * 5 + o];
          }
        }
      }
    }
  }
}

// ---- prep: batch moments of x per t ----
__global__ void k_moms(const float* __restrict__ x) {
  const int t = blockIdx.x, tid = threadIdx.x, lane = tid & 31, wid = tid >> 5;
  float s[5] = {0.f, 0.f, 0.f, 0.f, 0.f};
  for (int b = tid; b < 32768; b += 256) {
    float2 v = *reinterpret_cast<const float2*>(x + ((size_t)b * 128 + t) * 2);
    s[0] += v.x; s[1] += v.y; s[2] += v.x * v.x; s[3] += v.x * v.y; s[4] += v.y * v.y;
  }
  __shared__ float sh[5][8];
#pragma unroll
  for (int i = 0; i < 5; i++)
    for (int off = 16; off; off >>= 1) s[i] += __shfl_down_sync(0xffffffffu, s[i], off);
  if (lane == 0)
#pragma unroll
    for (int i = 0; i < 5; i++) sh[i][wid] = s[i];
  __syncthreads();
  if (tid == 0) {
#pragma unroll
    for (int i = 0; i < 5; i++) {
      float v = 0.f;
      for (int w = 0; w < 8; w++) v += sh[i][w];
      g_mom[t * 5 + i] = v;
    }
  }
}

// ---- prep: fold BN1 into per-(t,j) affine coefficients ----
__global__ void k_coef(const float* __restrict__ w_emb, const float* __restrict__ b_emb,
                       const float* __restrict__ gamma1,
                       const float* __restrict__ beta1) {
  const int t = blockIdx.x, j = threadIdx.x;
  const float invB = 1.f / 32768.f;
  float m0 = g_mom[t * 5 + 0] * invB, m1 = g_mom[t * 5 + 1] * invB;
  float c00 = g_mom[t * 5 + 2] * invB - m0 * m0;
  float c01 = g_mom[t * 5 + 3] * invB - m0 * m1;
  float c11 = g_mom[t * 5 + 4] * invB - m1 * m1;
  float w0 = w_emb[j * 2], w1 = w_emb[j * 2 + 1], bb = b_emb[j];
  float um = w0 * m0 + w1 * m1 + bb;
  float uv = w0 * w0 * c00 + 2.f * w0 * w1 * c01 + w1 * w1 * c11;
  float r = gamma1[j] * rsqrtf(uv + 1e-5f);
  g_ca[t * 128 + j] = r * w0;
  g_cb[t * 128 + j] = r * w1;
  g_cc[t * 128 + j] = r * (bb - um) + beta1[j];
}

// ---- prep: tf32-round + pack weights into slab/fragment order ----
__global__ void k_wsw(const float* __restrict__ w_ih, const float* __restrict__ w_hh,
                      const float* __restrict__ b_ih, const float* __restrict__ b_hh) {
  const int idx = blockIdx.x * 256 + threadIdx.x;  // 131072
  if (idx < 512) g_gb[idx] = b_ih[idx] + b_hh[idx];
  const int e = idx & 1, lane = (idx >> 1) & 31, nt = (idx >> 6) & 15;
  const int kt = (idx >> 10) & 3, s = idx >> 12;  // slab 0..31
  const int gmap[4] = {0, 2, 1, 3};               // stream i,g,f,o
  const int pg = gmap[s >> 3], part = (s >> 2) & 1;
  const int kl = (s & 3) * 32 + kt * 8 + (lane & 3) + 4 * e;
  const int n = pg * 128 + nt * 8 + (lane >> 2);
  const float* W = part ? w_hh : w_ih;
  g_W2[idx] = __uint_as_float(tf32u(W[n * 128 + kl]));
}

// ---- deferred BN2: stats over batch per (t, o) ----
__global__ void k_bnstats(const float* __restrict__ out) {
  const int t = blockIdx.x, tid = threadIdx.x, lane = tid & 31, wid = tid >> 5;
  float s[5] = {0.f, 0.f, 0.f, 0.f, 0.f}, qq[5] = {0.f, 0.f, 0.f, 0.f, 0.f};
  for (int b = tid; b < 32768; b += 256) {
    const float* p = out + ((size_t)b * 128 + t) * 5;
#pragma unroll
    for (int o = 0; o < 5; o++) { float v = p[o]; s[o] += v; qq[o] += v * v; }
  }
  __shared__ float sh[10][8];
#pragma unroll
  for (int o = 0; o < 5; o++)
    for (int off = 16; off; off >>= 1) {
      s[o] += __shfl_down_sync(0xffffffffu, s[o], off);
      qq[o] += __shfl_down_sync(0xffffffffu, qq[o], off);
    }
  if (lane == 0)
#pragma unroll
    for (int o = 0; o < 5; o++) { sh[o][wid] = s[o]; sh[5 + o][wid] = qq[o]; }
  __syncthreads();
  if (tid == 0) {
#pragma unroll
    for (int o = 0; o < 5; o++) {
      float S = 0.f, Q = 0.f;
      for (int w = 0; w < 8; w++) { S += sh[o][w]; Q += sh[5 + o][w]; }
      float mu = S / 32768.f, var = Q / 32768.f - mu * mu;
      g_mu2[t * 5 + o] = mu;
      g_rs2[t * 5 + o] = rsqrtf(var + 1e-5f);
    }
  }
}

// ---- deferred BN2: normalize + relu in place ----
__global__ void k_bnnorm(float* __restrict__ out, const float* __restrict__ gamma2,
                         const float* __restrict__ beta2) {
  size_t i = (size_t)blockIdx.x * 256 + threadIdx.x;
  if (i >= (size_t)32768 * 128 * 5) return;
  int o = (int)(i % 5);
  int t = (int)((i / 5) & 127);
  float v = out[i];
  out[i] = fmaxf(fmaf(gamma2[o] * g_rs2[t * 5 + o], v - g_mu2[t * 5 + o], beta2[o]), 0.f);
}

extern "C" void kernel_launch(void* const* d_in, const int* in_sizes, int n_in,
                              void* d_out, int out_size) {
  const float* x = (const float*)d_in[0];
  const float* w_emb = (const float*)d_in[1];
  const float* b_emb = (const float*)d_in[2];
  const float* gamma1 = (const float*)d_in[3];
  const float* beta1 = (const float*)d_in[4];
  const float* w_ih = (const float*)d_in[5];
  const float* w_hh = (const float*)d_in[6];
  const float* b_ih = (const float*)d_in[7];
  const float* b_hh = (const float*)d_in[8];
  const float* w_out = (const float*)d_in[9];
  const float* gamma2 = (const float*)d_in[11];
  const float* beta2 = (const float*)d_in[12];
  float* out = (float*)d_out;
  cudaFuncSetAttribute(k_main, cudaFuncAttributeMaxDynamicSharedMemorySize, SMEM_BYTES);
  k_moms<<<128, 256>>>(x);
  k_coef<<<128, 128>>>(w_emb, b_emb, gamma1, beta1);
  k_wsw<<<512, 256>>>(w_ih, w_hh, b_ih, b_hh);
  k_main<<<512, 128, SMEM_BYTES>>>(x, w_out, out);
  k_bnstats<<<128, 256>>>(out);
  k_bnnorm<<<81920, 256>>>(out, gamma2, beta2);
}

// round 14
// speedup vs baseline: 1.0344x; 1.0344x over previous
#include <cuda_runtime.h>
#include <cstdint>
#include <cstddef>

#define HLD 132
#define ESZ (64 * HLD)  // 8448 floats
// smem floats: Wb 10240 (5 bufs x [cg2][1024]) | E 8448 | H 8448 | ws 640 | gbs 512 | zb 320
#define SMEM_FLOATS (10240 + ESZ + ESZ + 640 + 512 + 320)
#define SMEM_BYTES (SMEM_FLOATS * 4)

// [subslab64][cg2][kt2][ntl8][lane32][e2] tf32
__device__ __align__(16) float g_W2[131072];
__device__ float g_gb[512];
__device__ float g_ca[16384], g_cb[16384], g_cc[16384];
__device__ float g_mom[640];
__device__ float g_mu2[640], g_rs2[640];

__device__ __forceinline__ uint32_t tf32u(float f) {
  uint32_t u;
  asm("cvt.rna.tf32.f32 %0,%1;" : "=r"(u) : "f"(f));
  return u;
}
__device__ __forceinline__ float tf32f(float f) { return __uint_as_float(tf32u(f)); }
__device__ __forceinline__ float tanh_ap(float x) {
  float y;
  asm("tanh.approx.f32 %0,%1;" : "=f"(y) : "f"(x));
  return y;
}
__device__ __forceinline__ float sig_ap(float x) {
  return fmaf(tanh_ap(0.5f * x), 0.5f, 0.5f);
}
__device__ __forceinline__ void mma8(float (&d)[4], float a0, float a1, float a2,
                                     float a3, float b0, float b1) {
  asm volatile(
      "mma.sync.aligned.m16n8k8.row.col.f32.tf32.tf32.f32 "
      "{%0,%1,%2,%3},{%4,%5,%6,%7},{%8,%9},{%0,%1,%2,%3};\n"
      : "+f"(d[0]), "+f"(d[1]), "+f"(d[2]), "+f"(d[3])
      : "r"(__float_as_uint(a0)), "r"(__float_as_uint(a1)),
        "r"(__float_as_uint(a2)), "r"(__float_as_uint(a3)),
        "r"(__float_as_uint(b0)), "r"(__float_as_uint(b1)));
}
// 4KB half-sub-slab copy: 64 threads (one cg pair) x 64B each.
__device__ __forceinline__ void issue_half(float* Wb, int content, int buf, int cg,
                                           int ctid) {
  uint32_t sa = (uint32_t)__cvta_generic_to_shared(Wb + buf * 2048 + cg * 1024 +
                                                   ctid * 16);
  const char* gp =
      (const char*)(g_W2 + (size_t)content * 2048 + cg * 1024 + ctid * 16);
#pragma unroll
  for (int i = 0; i < 4; i++)
    asm volatile("cp.async.cg.shared.global [%0], [%1], 16;" ::"r"(sa + 16 * i),
                 "l"(gp + 16 * i));
  asm volatile("cp.async.commit_group;" ::: "memory");
}
__device__ __forceinline__ void pair_bar(int cg) {
  asm volatile("bar.sync %0, %1;" ::"r"(1 + cg), "r"(64) : "memory");
}

// ---- main recurrent kernel: 512 CTAs x 128 thr (2 CTAs/SM), 64 rows/CTA ----
__global__ void __launch_bounds__(128, 2)
    k_main(const float* __restrict__ x, const float* __restrict__ wout,
           float* __restrict__ out) {
  extern __shared__ float sm[];
  float* Wb = sm;
  float* E = sm + 10240;
  float* H = E + ESZ;
  float* ws = H + ESZ;
  float* gbs = ws + 640;
  float* zb = gbs + 512;
  const int tid = threadIdx.x, lane = tid & 31, wid = tid >> 5;
  const int rg = wid >> 1, cg = wid & 1, lg = lane >> 2, q = lane & 3;
  const int ctid = rg * 32 + lane;  // id within the 64-thread cg pair
  const int bg0 = blockIdx.x << 6;
  for (int i = tid; i < 640; i += 128) ws[i] = wout[i];
  for (int i = tid; i < 512; i += 128) gbs[i] = g_gb[i];
  for (int i = tid; i < ESZ; i += 128) H[i] = 0.f;
  float c[2][8][4], acc[2][8][4], ig[2][8][4];
#pragma unroll
  for (int m = 0; m < 2; m++)
#pragma unroll
    for (int nt = 0; nt < 8; nt++)
#pragma unroll
      for (int e = 0; e < 4; e++) c[m][nt][e] = 0.f;
  __syncthreads();
  // stagger co-resident CTAs so their stall phases interleave (no output effect)
  if (blockIdx.x & 1) {
    unsigned long long t0 = clock64();
    while (clock64() - t0 < 800ull) {}
  }
  const int er = tid >> 1;
  const size_t xo = (size_t)(bg0 + er) * 256;
  const int ar = (32 * rg + lg) * HLD;
  const int bofs[4] = {0, 256, 128, 384};  // stream i,g,f,o -> pytorch offsets

  // prologue: depth-3 — own halves of sub-slabs 0,1,2 into ring bufs 0,1,2
  issue_half(Wb, 0, 0, cg, ctid);
  issue_half(Wb, 1, 1, cg, ctid);
  issue_half(Wb, 2, 2, cg, ctid);
  int ibuf = 3, cbuf = 0;  // ring-of-5 cursors (identical across pair members)

  for (int t = 0; t < 128; t++) {
    // ---- E fill: e = relu(ca*x0+cb*x1+cc), tf32-rounded (BN1 folded) ----
    {
      float2 xv = *reinterpret_cast<const float2*>(x + xo + 2 * t);
      const int jb = (tid & 1) << 4;
      const float4* A4 = reinterpret_cast<const float4*>(g_ca + t * 128) + jb;
      const float4* B4 = reinterpret_cast<const float4*>(g_cb + t * 128) + jb;
      const float4* C4 = reinterpret_cast<const float4*>(g_cc + t * 128) + jb;
      float* Er = E + er * HLD + ((tid & 1) << 6);
#pragma unroll
      for (int i = 0; i < 16; i++) {
        float4 a = A4[i], b = B4[i], cc4 = C4[i], ev;
        ev.x = tf32f(fmaxf(fmaf(a.x, xv.x, fmaf(b.x, xv.y, cc4.x)), 0.f));
        ev.y = tf32f(fmaxf(fmaf(a.y, xv.x, fmaf(b.y, xv.y, cc4.y)), 0.f));
        ev.z = tf32f(fmaxf(fmaf(a.z, xv.x, fmaf(b.z, xv.y, cc4.z)), 0.f));
        ev.w = tf32f(fmaxf(fmaf(a.w, xv.x, fmaf(b.w, xv.y, cc4.w)), 0.f));
        *reinterpret_cast<float4*>(Er + 4 * i) = ev;
      }
    }
    __syncthreads();  // E(t) fully written before any pair consumes it
    for (int ss = 0; ss < 64; ss++) {
      if ((ss & 15) == 0) {
#pragma unroll
        for (int m = 0; m < 2; m++)
#pragma unroll
          for (int nt = 0; nt < 8; nt++)
#pragma unroll
            for (int e = 0; e < 4; e++) acc[m][nt][e] = 0.f;
      }
      // per-pair pipeline: pair bar at iter ss-1 separates consume(ss-2) from
      // this overwrite of its buffer; only this 64-thread pair touches the half.
      issue_half(Wb, (ss + 3) & 63, ibuf, cg, ctid);
      ibuf = (ibuf == 4) ? 0 : ibuf + 1;
      asm volatile("cp.async.wait_group 3;" ::: "memory");
      pair_bar(cg);
      // ---- consume own half of sub-slab ss: 2 k-tiles, 32 rows x 64 cols ----
      const float* Ab = ((ss >> 3) & 1) ? H : E;
      const float2* Bh =
          reinterpret_cast<const float2*>(Wb + cbuf * 2048 + cg * 1024);
      cbuf = (cbuf == 4) ? 0 : cbuf + 1;
      const int kb = ((ss >> 1) & 3) * 32 + (ss & 1) * 16;
#pragma unroll
      for (int kt = 0; kt < 2; kt++) {
        const float* ap = Ab + ar + kb + kt * 8 + q;
        float a00 = ap[0], a01 = ap[8 * HLD], a02 = ap[4], a03 = ap[8 * HLD + 4];
        float a10 = ap[16 * HLD], a11 = ap[24 * HLD];
        float a12 = ap[16 * HLD + 4], a13 = ap[24 * HLD + 4];
        const float2* bp = Bh + kt * 256 + lane;
#pragma unroll
        for (int nt = 0; nt < 8; nt++) {
          float2 bv = bp[nt * 32];
          mma8(acc[0][nt], a00, a01, a02, a03, bv.x, bv.y);
          mma8(acc[1][nt], a10, a11, a12, a13, bv.x, bv.y);
        }
      }
      if ((ss & 15) != 15) continue;
      const int sg = ss >> 4;
      const float* gb = gbs + bofs[sg] + cg * 64 + 2 * q;
      if (sg == 0) {  // i-gate
#pragma unroll
        for (int m = 0; m < 2; m++)
#pragma unroll
          for (int nt = 0; nt < 8; nt++) {
            float2 gv = *reinterpret_cast<const float2*>(gb + 8 * nt);
            ig[m][nt][0] = sig_ap(acc[m][nt][0] + gv.x);
            ig[m][nt][1] = sig_ap(acc[m][nt][1] + gv.y);
            ig[m][nt][2] = sig_ap(acc[m][nt][2] + gv.x);
            ig[m][nt][3] = sig_ap(acc[m][nt][3] + gv.y);
          }
      } else if (sg == 1) {  // g-gate
#pragma unroll
        for (int m = 0; m < 2; m++)
#pragma unroll
          for (int nt = 0; nt < 8; nt++) {
            float2 gv = *reinterpret_cast<const float2*>(gb + 8 * nt);
            ig[m][nt][0] *= tanh_ap(acc[m][nt][0] + gv.x);
            ig[m][nt][1] *= tanh_ap(acc[m][nt][1] + gv.y);
            ig[m][nt][2] *= tanh_ap(acc[m][nt][2] + gv.x);
            ig[m][nt][3] *= tanh_ap(acc[m][nt][3] + gv.y);
          }
      } else if (sg == 2) {  // f-gate
#pragma unroll
        for (int m = 0; m < 2; m++)
#pragma unroll
          for (int nt = 0; nt < 8; nt++) {
            float2 gv = *reinterpret_cast<const float2*>(gb + 8 * nt);
            c[m][nt][0] = fmaf(sig_ap(acc[m][nt][0] + gv.x), c[m][nt][0], ig[m][nt][0]);
            c[m][nt][1] = fmaf(sig_ap(acc[m][nt][1] + gv.y), c[m][nt][1], ig[m][nt][1]);
            c[m][nt][2] = fmaf(sig_ap(acc[m][nt][2] + gv.x), c[m][nt][2], ig[m][nt][2]);
            c[m][nt][3] = fmaf(sig_ap(acc[m][nt][3] + gv.y), c[m][nt][3], ig[m][nt][3]);
          }
      } else {  // o-gate: h, H store, z2 partials
        // FULL barrier: collects ALL H reads from BOTH pairs (laggard pair blocks
        // release until its own iter-63 consume is done) before H rewrite.
        __syncthreads();
        float zr[4][5];
#pragma unroll
        for (int sl = 0; sl < 4; sl++)
#pragma unroll
          for (int o = 0; o < 5; o++) zr[sl][o] = 0.f;
#pragma unroll
        for (int m = 0; m < 2; m++)
#pragma unroll
          for (int nt = 0; nt < 8; nt++) {
            float2 gv = *reinterpret_cast<const float2*>(gb + 8 * nt);
            float h0 = sig_ap(acc[m][nt][0] + gv.x) * tanh_ap(c[m][nt][0]);
            float h1 = sig_ap(acc[m][nt][1] + gv.y) * tanh_ap(c[m][nt][1]);
            float h2 = sig_ap(acc[m][nt][2] + gv.x) * tanh_ap(c[m][nt][2]);
            float h3 = sig_ap(acc[m][nt][3] + gv.y) * tanh_ap(c[m][nt][3]);
            const int col = cg * 64 + nt * 8 + 2 * q;
            const int ro = ar + 16 * m * HLD + col;
            *reinterpret_cast<float2*>(H + ro) = make_float2(tf32f(h0), tf32f(h1));
            *reinterpret_cast<float2*>(H + ro + 8 * HLD) =
                make_float2(tf32f(h2), tf32f(h3));
#pragma unroll
            for (int o = 0; o < 5; o++) {
              float2 wv = *reinterpret_cast<const float2*>(ws + o * 128 + col);
              zr[2 * m][o] = fmaf(h0, wv.x, fmaf(h1, wv.y, zr[2 * m][o]));
              zr[2 * m + 1][o] = fmaf(h2, wv.x, fmaf(h3, wv.y, zr[2 * m + 1][o]));
            }
          }
#pragma unroll
        for (int sl = 0; sl < 4; sl++)
#pragma unroll
          for (int o = 0; o < 5; o++) {
            zr[sl][o] += __shfl_xor_sync(0xffffffffu, zr[sl][o], 1);
            zr[sl][o] += __shfl_xor_sync(0xffffffffu, zr[sl][o], 2);
          }
        if (cg == 0 && q == 0) {
#pragma unroll
          for (int sl = 0; sl < 4; sl++)
#pragma unroll
            for (int o = 0; o < 5; o++)
              zb[(32 * rg + lg + 8 * sl) * 5 + o] = zr[sl][o];
        }
        __syncthreads();
        if (cg == 1 && q == 0) {
#pragma unroll
          for (int sl = 0; sl < 4; sl++) {
            int row = 32 * rg + lg + 8 * sl;
            size_t ob = ((size_t)(bg0 + row) * 128 + t) * 5;
#pragma unroll
            for (int o = 0; o < 5; o++) out[ob + o] = zr[sl][o] + zb[row * 5 + o];
          }
        }
      }
    }
  }
}

// ---- prep: batch moments of x per t ----
__global__ void k_moms(const float* __restrict__ x) {
  const int t = blockIdx.x, tid = threadIdx.x, lane = tid & 31, wid = tid >> 5;
  float s[5] = {0.f, 0.f, 0.f, 0.f, 0.f};
  for (int b = tid; b < 32768; b += 256) {
    float2 v = *reinterpret_cast<const float2*>(x + ((size_t)b * 128 + t) * 2);
    s[0] += v.x; s[1] += v.y; s[2] += v.x * v.x; s[3] += v.x * v.y; s[4] += v.y * v.y;
  }
  __shared__ float sh[5][8];
#pragma unroll
  for (int i = 0; i < 5; i++)
    for (int off = 16; off; off >>= 1) s[i] += __shfl_down_sync(0xffffffffu, s[i], off);
  if (lane == 0)
#pragma unroll
    for (int i = 0; i < 5; i++) sh[i][wid] = s[i];
  __syncthreads();
  if (tid == 0) {
#pragma unroll
    for (int i = 0; i < 5; i++) {
      float v = 0.f;
      for (int w = 0; w < 8; w++) v += sh[i][w];
      g_mom[t * 5 + i] = v;
    }
  }
}

// ---- prep: fold BN1 into per-(t,j) affine coefficients ----
__global__ void k_coef(const float* __restrict__ w_emb, const float* __restrict__ b_emb,
                       const float* __restrict__ gamma1,
                       const float* __restrict__ beta1) {
  const int t = blockIdx.x, j = threadIdx.x;
  const float invB = 1.f / 32768.f;
  float m0 = g_mom[t * 5 + 0] * invB, m1 = g_mom[t * 5 + 1] * invB;
  float c00 = g_mom[t * 5 + 2] * invB - m0 * m0;
  float c01 = g_mom[t * 5 + 3] * invB - m0 * m1;
  float c11 = g_mom[t * 5 + 4] * invB - m1 * m1;
  float w0 = w_emb[j * 2], w1 = w_emb[j * 2 + 1], bb = b_emb[j];
  float um = w0 * m0 + w1 * m1 + bb;
  float uv = w0 * w0 * c00 + 2.f * w0 * w1 * c01 + w1 * w1 * c11;
  float r = gamma1[j] * rsqrtf(uv + 1e-5f);
  g_ca[t * 128 + j] = r * w0;
  g_cb[t * 128 + j] = r * w1;
  g_cc[t * 128 + j] = r * (bb - um) + beta1[j];
}

// ---- prep: tf32-round + pack weights, cg-major halves per sub-slab ----
__global__ void k_wsw(const float* __restrict__ w_ih, const float* __restrict__ w_hh,
                      const float* __restrict__ b_ih, const float* __restrict__ b_hh) {
  const int idx = blockIdx.x * 256 + threadIdx.x;  // 131072
  if (idx < 512) g_gb[idx] = b_ih[idx] + b_hh[idx];
  const int e = idx & 1, lane = (idx >> 1) & 31, ntl = (idx >> 6) & 7;
  const int kt = (idx >> 9) & 1, cgb = (idx >> 10) & 1, ss = idx >> 11;  // 0..63
  const int gmap[4] = {0, 2, 1, 3};  // stream i,g,f,o
  const int pg = gmap[ss >> 4], part = (ss >> 3) & 1;
  const int k = ((ss >> 1) & 3) * 32 + (ss & 1) * 16 + kt * 8 + (lane & 3) + 4 * e;
  const int n = pg * 128 + (cgb * 8 + ntl) * 8 + (lane >> 2);
  const float* W = part ? w_hh : w_ih;
  g_W2[idx] = __uint_as_float(tf32u(W[n * 128 + k]));
}

// ---- deferred BN2: stats over batch per (t, o) ----
__global__ void k_bnstats(const float* __restrict__ out) {
  const int t = blockIdx.x, tid = threadIdx.x, lane = tid & 31, wid = tid >> 5;
  float s[5] = {0.f, 0.f, 0.f, 0.f, 0.f}, qq[5] = {0.f, 0.f, 0.f, 0.f, 0.f};
  for (int b = tid; b < 32768; b += 256) {
    const float* p = out + ((size_t)b * 128 + t) * 5;
#pragma unroll
    for (int o = 0; o < 5; o++) { float v = p[o]; s[o] += v; qq[o] += v * v; }
  }
  __shared__ float sh[10][8];
#pragma unroll
  for (int o = 0; o < 5; o++)
    for (int off = 16; off; off >>= 1) {
      s[o] += __shfl_down_sync(0xffffffffu, s[o], off);
      qq[o] += __shfl_down_sync(0xffffffffu, qq[o], off);
    }
  if (lane == 0)
#pragma unroll
    for (int o = 0; o < 5; o++) { sh[o][wid] = s[o]; sh[5 + o][wid] = qq[o]; }
  __syncthreads();
  if (tid == 0) {
#pragma unroll
    for (int o = 0; o < 5; o++) {
      float S = 0.f, Q = 0.f;
      for (int w = 0; w < 8; w++) { S += sh[o][w]; Q += sh[5 + o][w]; }
      float mu = S / 32768.f, var = Q / 32768.f - mu * mu;
      g_mu2[t * 5 + o] = mu;
      g_rs2[t * 5 + o] = rsqrtf(var + 1e-5f);
    }
  }
}

// ---- deferred BN2: normalize + relu in place ----
__global__ void k_bnnorm(float* __restrict__ out, const float* __restrict__ gamma2,
                         const float* __restrict__ beta2) {
  size_t i = (size_t)blockIdx.x * 256 + threadIdx.x;
  if (i >= (size_t)32768 * 128 * 5) return;
  int o = (int)(i % 5);
  int t = (int)((i / 5) & 127);
  float v = out[i];
  out[i] = fmaxf(fmaf(gamma2[o] * g_rs2[t * 5 + o], v - g_mu2[t * 5 + o], beta2[o]), 0.f);
}

extern "C" void kernel_launch(void* const* d_in, const int* in_sizes, int n_in,
                              void* d_out, int out_size) {
  const float* x = (const float*)d_in[0];
  const float* w_emb = (const float*)d_in[1];
  const float* b_emb = (const float*)d_in[2];
  const float* gamma1 = (const float*)d_in[3];
  const float* beta1 = (const float*)d_in[4];
  const float* w_ih = (const float*)d_in[5];
  const float* w_hh = (const float*)d_in[6];
  const float* b_ih = (const float*)d_in[7];
  const float* b_hh = (const float*)d_in[8];
  const float* w_out = (const float*)d_in[9];
  const float* gamma2 = (const float*)d_in[11];
  const float* beta2 = (const float*)d_in[12];
  float* out = (float*)d_out;
  cudaFuncSetAttribute(k_main, cudaFuncAttributeMaxDynamicSharedMemorySize, SMEM_BYTES);
  k_moms<<<128, 256>>>(x);
  k_coef<<<128, 128>>>(w_emb, b_emb, gamma1, beta1);
  k_wsw<<<512, 256>>>(w_ih, w_hh, b_ih, b_hh);
  k_main<<<512, 128, SMEM_BYTES>>>(x, w_out, out);
  k_bnstats<<<128, 256>>>(out);
  k_bnnorm<<<81920, 256>>>(out, gamma2, beta2);
}